// round 4
// baseline (speedup 1.0000x reference)
#include <cuda_runtime.h>
#include <cstdint>
#include <cstddef>

#define TT 2048
#define BB 64

// 512 MB scratch: precomputed input projections [2][B*T][512]
__device__ float g_zpre[(size_t)2 * BB * TT * 512];

// ---------------- packed f32x2 helpers ----------------
__device__ __forceinline__ unsigned long long pk2(float lo, float hi) {
    unsigned long long r;
    asm("mov.b64 %0, {%1,%2};" : "=l"(r) : "f"(lo), "f"(hi));
    return r;
}
__device__ __forceinline__ void upk2(unsigned long long v, float& lo, float& hi) {
    asm("mov.b64 {%0,%1}, %2;" : "=f"(lo), "=f"(hi) : "l"(v));
}
__device__ __forceinline__ unsigned long long ffma2(unsigned long long a,
                                                    unsigned long long b,
                                                    unsigned long long c) {
    unsigned long long d;
    asm("fma.rn.f32x2 %0, %1, %2, %3;" : "=l"(d) : "l"(a), "l"(b), "l"(c));
    return d;
}
__device__ __forceinline__ float sigm(float x) {
    return __fdividef(1.0f, 1.0f + __expf(-x));
}
__device__ __forceinline__ float tanh_f(float x) {
    float ax = fabsf(x);
    float e  = __expf(-2.0f * ax);
    float r  = __fdividef(1.0f - e, 1.0f + e);
    return x < 0.0f ? -r : r;
}

// ---------------------------------------------------------------------------
// Phase 1: Zpre = x @ W[0:128,:] + b.
// grid (4 col-tiles, 1024 row-tiles, 2 dirs), 256 threads = 32 tx * 8 ty.
// Thread tile: 16 rows x 4 cols. K chunked by 32 into static smem.
// ---------------------------------------------------------------------------
__global__ void __launch_bounds__(256, 1)
lstm_pre(const float* __restrict__ x,
         const float* __restrict__ W0, const float* __restrict__ bias0,
         const float* __restrict__ W1, const float* __restrict__ bias1) {
    __shared__ float xs[128 * 32];   // [row][k]
    __shared__ float ws[32 * 128];   // [k][col]

    const int dir = blockIdx.z;
    const float* W    = dir ? W1 : W0;
    const float* bias = dir ? bias1 : bias0;
    const size_t m0 = (size_t)blockIdx.y * 128;
    const int    c0 = blockIdx.x * 128;
    const int tid = threadIdx.x;
    const int tx = tid & 31;   // col group (4 cols)
    const int ty = tid >> 5;   // row group (16 rows)

    unsigned long long acc[16][2];
    #pragma unroll
    for (int i = 0; i < 16; ++i) { acc[i][0] = 0ull; acc[i][1] = 0ull; }

    for (int kc = 0; kc < 4; ++kc) {
        if (kc) __syncthreads();
        #pragma unroll
        for (int i = tid; i < 1024; i += 256) {   // xs: 1024 float4
            int r = i >> 3, kq = i & 7;
            *(float4*)(xs + r * 32 + kq * 4) =
                *(const float4*)(x + (m0 + r) * 128 + kc * 32 + kq * 4);
        }
        #pragma unroll
        for (int i = tid; i < 1024; i += 256) {   // ws: 1024 float4
            int k = i >> 5, c4 = (i & 31) * 4;
            *(float4*)(ws + k * 128 + c4) =
                *(const float4*)(W + (size_t)(kc * 32 + k) * 512 + c0 + c4);
        }
        __syncthreads();

        #pragma unroll
        for (int kq = 0; kq < 8; ++kq) {
            float4 av[16];
            #pragma unroll
            for (int i = 0; i < 16; ++i)
                av[i] = *(const float4*)(xs + (ty * 16 + i) * 32 + kq * 4);
            #pragma unroll
            for (int kk = 0; kk < 4; ++kk) {
                ulonglong2 bv = *(const ulonglong2*)(ws + (kq * 4 + kk) * 128 + tx * 4);
                #pragma unroll
                for (int i = 0; i < 16; ++i) {
                    float a = (kk == 0) ? av[i].x : (kk == 1) ? av[i].y
                            : (kk == 2) ? av[i].z : av[i].w;
                    unsigned long long ap = pk2(a, a);
                    acc[i][0] = ffma2(ap, bv.x, acc[i][0]);
                    acc[i][1] = ffma2(ap, bv.y, acc[i][1]);
                }
            }
        }
    }

    float bl0 = bias[c0 + tx * 4 + 0], bl1 = bias[c0 + tx * 4 + 1];
    float bl2 = bias[c0 + tx * 4 + 2], bl3 = bias[c0 + tx * 4 + 3];
    #pragma unroll
    for (int i = 0; i < 16; ++i) {
        float v0, v1, v2, v3;
        upk2(acc[i][0], v0, v1);
        upk2(acc[i][1], v2, v3);
        float4 o = make_float4(v0 + bl0, v1 + bl1, v2 + bl2, v3 + bl3);
        *(float4*)(g_zpre + ((size_t)dir * (BB * TT) + m0 + ty * 16 + i) * 512
                   + c0 + tx * 4) = o;
    }
}

// ---------------------------------------------------------------------------
// Phase 2: recurrence. 64 clusters of 2 CTAs (128 CTAs total, one wave).
// Cluster cid -> dir = cid/32, batch rows b0 = 2*(cid%32), b0+1.
// CTA rank owns z-cols {g*128 + rank*64 + u}, W_h half register-resident.
// h exchanged via DSMEM store + per-step cluster barrier.
// ---------------------------------------------------------------------------
__global__ void __cluster_dims__(2, 1, 1) __launch_bounds__(256, 1)
lstm_rec(const float* __restrict__ Wfw, const float* __restrict__ Wbw,
         float* __restrict__ out) {
    __shared__ __align__(16) float hbuf[2][2][128];  // [parity][row][unit]
    __shared__ float zbuf[2][256];                   // [row][local col]

    uint32_t rank;
    asm("mov.u32 %0, %%cluster_ctarank;" : "=r"(rank));
    const uint32_t peer = rank ^ 1u;
    const int cid = blockIdx.x >> 1;
    const int dir = cid >> 5;
    const int b0  = (cid & 31) * 2;
    const int tid = threadIdx.x;
    const int g   = tid >> 6;                         // gate 0..3 (i,j,f,o)
    const int ul  = tid & 63;                         // unit within half
    const int col = g * 128 + (int)rank * 64 + ul;    // owned z column
    const float* W = dir ? Wbw : Wfw;

    // W_h column -> registers, packed over k-pairs (rows 128..255 of W)
    unsigned long long w2[64];
    #pragma unroll
    for (int kp = 0; kp < 64; ++kp)
        w2[kp] = pk2(W[(size_t)(128 + 2 * kp) * 512 + col],
                     W[(size_t)(129 + 2 * kp) * 512 + col]);

    for (int i = tid; i < 512; i += 256) ((float*)hbuf)[i] = 0.0f;

    // z_pre streaming pointers (row b0 and b0+1)
    const int tq0 = dir ? (TT - 1) : 0;
    const ptrdiff_t dstep = dir ? -512 : 512;
    const float* zp0 = g_zpre + ((size_t)dir * (BB * TT) + (size_t)b0 * TT + tq0) * 512 + col;
    const float* zp1 = zp0 + (size_t)TT * 512;
    float zc0 = __ldcs(zp0), zc1 = __ldcs(zp1);

    float c_state = 0.0f;
    const int grow = (tid >> 6) & 1;   // gate-thread batch row (tid<128)
    const int gu   = tid & 63;         // gate-thread unit

    __syncthreads();
    asm volatile("barrier.cluster.arrive.aligned;" ::: "memory");
    asm volatile("barrier.cluster.wait.aligned;"   ::: "memory");

    for (int t = 0; t < TT; ++t) {
        const int p = t & 1;

        float zn0 = 0.0f, zn1 = 0.0f;           // prefetch next step
        if (t + 1 < TT) {
            zp0 += dstep; zp1 += dstep;
            zn0 = __ldcs(zp0); zn1 = __ldcs(zp1);
        }

        unsigned long long a0 = 0ull, a1 = 0ull;   // z = h @ W_h[:,col]
        #pragma unroll
        for (int q = 0; q < 32; ++q) {
            ulonglong2 h0 = *(const ulonglong2*)(&hbuf[p][0][q * 4]);
            ulonglong2 h1 = *(const ulonglong2*)(&hbuf[p][1][q * 4]);
            a0 = ffma2(h0.x, w2[2 * q],     a0);
            a0 = ffma2(h0.y, w2[2 * q + 1], a0);
            a1 = ffma2(h1.x, w2[2 * q],     a1);
            a1 = ffma2(h1.y, w2[2 * q + 1], a1);
        }
        float s0l, s0h, s1l, s1h;
        upk2(a0, s0l, s0h);
        upk2(a1, s1l, s1h);
        zbuf[0][tid] = s0l + s0h + zc0;
        zbuf[1][tid] = s1l + s1h + zc1;
        zc0 = zn0; zc1 = zn1;
        __syncthreads();

        if (tid < 128) {                         // one thread per (row, unit)
            float zi = zbuf[grow][gu];
            float zj = zbuf[grow][64  + gu];
            float zf = zbuf[grow][128 + gu];
            float zo = zbuf[grow][192 + gu];
            c_state = c_state * sigm(zf + 1.0f) + sigm(zi) * tanh_f(zj);
            float hn = sigm(zo) * tanh_f(c_state);

            const int pn = p ^ 1;
            const int ug = (int)rank * 64 + gu;
            hbuf[pn][grow][ug] = hn;
            uint32_t la = (uint32_t)__cvta_generic_to_shared(&hbuf[pn][grow][ug]);
            uint32_t ra;
            asm("mapa.shared::cluster.u32 %0, %1, %2;" : "=r"(ra) : "r"(la), "r"(peer));
            asm volatile("st.shared::cluster.f32 [%0], %1;" :: "r"(ra), "f"(hn));

            const int tq = dir ? (TT - 1 - t) : t;
            out[((size_t)(b0 + grow) * TT + tq) * 256 + dir * 128 + ug] = hn;
        }
        asm volatile("barrier.cluster.arrive.aligned;" ::: "memory");
        asm volatile("barrier.cluster.wait.aligned;"   ::: "memory");
    }
}

extern "C" void kernel_launch(void* const* d_in, const int* in_sizes, int n_in,
                              void* d_out, int out_size) {
    const float* x   = (const float*)d_in[0];
    const float* Wfw = (const float*)d_in[1];
    const float* bfw = (const float*)d_in[2];
    const float* Wbw = (const float*)d_in[3];
    const float* bbw = (const float*)d_in[4];
    float* out = (float*)d_out;

    dim3 g1(4, 1024, 2);
    lstm_pre<<<g1, 256>>>(x, Wfw, bfw, Wbw, bbw);
    lstm_rec<<<128, 256>>>(Wfw, Wbw, out);
}